// round 6
// baseline (speedup 1.0000x reference)
#include <cuda_runtime.h>
#include <cuda_fp16.h>
#include <cstdint>

// Problem dims
static constexpr int M = 256;
static constexpr int K = 4096;
static constexpr int N = 8192;
static constexpr int KITERS = K / 64;     // 64 K-chunks of 64

// SMEM layout (per 128-thread CTA, tile 64x64):
//  [0,1024)            header (unused, alignment)
//  [1024, +3*8192)     A fragment ring: 3 stages x 8KB (4 mi x 4 ks x 32 lanes x 16B)
//  [25600, +2*8192)    B dequant double buffer (64 rows x 128B each)
static constexpr int SMEM_A = 1024;
static constexpr int SMEM_B = 1024 + 3 * 8192;       // 25600
static constexpr int SMEM_TOTAL = SMEM_B + 2 * 8192; // 41984

// A in m16n8k16 fragment layout, fp16, built by convert kernel.
// Index: ((mi * (K/16) + ki) * 32 + lane) -> uint4 (regs a0,a1,a2,a3)
__device__ uint4 g_xa[(M / 16) * (K / 16) * 32];

// ---------------- helpers ----------------

__device__ __forceinline__ uint32_t smem_u32(const void* p) {
    uint32_t a;
    asm("{ .reg .u64 t; cvta.to.shared.u64 t, %1; cvt.u32.u64 %0, t; }"
        : "=r"(a) : "l"(p));
    return a;
}

__device__ __forceinline__ uint32_t sw128(uint32_t off) {
    return off ^ ((off >> 3) & 0x70);
}

// Dequant one 16-weight group (4 int32, low byte each = 4 x 2-bit codes)
// into 8 u32 = 16 fp16, via a 4-entry fp16 LUT + PRMT byte gather.
__device__ __forceinline__ void dequant16(const int4& p4, float n, uint32_t o[8]) {
    uint32_t b1 = (uint32_t)__half_as_ushort(__float2half_rn(n));
    uint32_t b3 = (uint32_t)__half_as_ushort(__float2half_rn(n * (1.0f / 3.0f)));
    uint32_t loT = (b1 ^ 0x8000u) | ((b3 ^ 0x8000u) << 16);  // bytes: [-n][-n/3]
    uint32_t hiT = b3 | (b1 << 16);                          // bytes: [n/3][n]
    uint32_t pv[4] = { (uint32_t)p4.x, (uint32_t)p4.y, (uint32_t)p4.z, (uint32_t)p4.w };
    #pragma unroll
    for (int q = 0; q < 4; ++q) {
        uint32_t by = pv[q] & 0xFFu;   // 4 x 2-bit codes
        uint32_t l = by & 0xFu;
        uint32_t h = by >> 4;
        uint32_t c0 = (l & 3u) * 0x22u + (l & 0xCu) * 0x880u + 0x1010u;
        uint32_t c1 = (h & 3u) * 0x22u + (h & 0xCu) * 0x880u + 0x1010u;
        o[2 * q]     = __byte_perm(loT, hiT, c0);
        o[2 * q + 1] = __byte_perm(loT, hiT, c1);
    }
}

// ---------------- kernel 0: x fp32 -> A-fragment fp16 layout ----------------

__global__ void convert_x_frag(const float* __restrict__ x) {
    int g = blockIdx.x * blockDim.x + threadIdx.x;   // 0 .. 131071
    int lane = g & 31;
    int ki = (g >> 5) & (K / 16 - 1);
    int mi = g >> 13;
    int r = lane >> 2;
    int c = (lane & 3) * 2;
    const float* base = x + (size_t)(mi * 16 + r) * K + ki * 16 + c;
    float2 v00 = *reinterpret_cast<const float2*>(base);
    float2 v10 = *reinterpret_cast<const float2*>(base + 8 * K);
    float2 v01 = *reinterpret_cast<const float2*>(base + 8);
    float2 v11 = *reinterpret_cast<const float2*>(base + 8 * K + 8);
    uint4 o;
    o.x = (uint32_t)__half_as_ushort(__float2half_rn(v00.x)) |
          ((uint32_t)__half_as_ushort(__float2half_rn(v00.y)) << 16);
    o.y = (uint32_t)__half_as_ushort(__float2half_rn(v10.x)) |
          ((uint32_t)__half_as_ushort(__float2half_rn(v10.y)) << 16);
    o.z = (uint32_t)__half_as_ushort(__float2half_rn(v01.x)) |
          ((uint32_t)__half_as_ushort(__float2half_rn(v01.y)) << 16);
    o.w = (uint32_t)__half_as_ushort(__float2half_rn(v11.x)) |
          ((uint32_t)__half_as_ushort(__float2half_rn(v11.y)) << 16);
    g_xa[g] = o;
}

// ---------------- kernel 1: fused dequant + fp16 HMMA GEMM ----------------
// Grid (128, 4): blockIdx.x = N-tile (64 cols), blockIdx.y = M-tile (64 rows)
// 128 threads = 4 warps as 2(M) x 2(N); warp tile 32x32.
// A: cp.async gmem->SMEM ring (3 stages, issued 2 iters ahead), LDS.128 per ks.
// B: packed LDG 1 iter ahead -> dequant -> SMEM (SW128) -> ldmatrix, 2 buffers.
// 5 CTAs/SM resident (SMEM-bound): 20 warps/SM.

__global__ void __launch_bounds__(128, 5)
linear2bit_gemm(const int4* __restrict__ wq,        // one int4 = one 16-value group
                const void* __restrict__ wn_raw,    // [NUM_GROUPS] norms (fp32 or fp16)
                const float* __restrict__ bias,     // [N]
                float* __restrict__ out)            // [M, N]
{
    extern __shared__ char smem[];
    const uint32_t sb = smem_u32(smem);
    const int tid = threadIdx.x;
    const int wid = tid >> 5;
    const int lid = tid & 31;
    const int ntile = blockIdx.x;                   // 64-col tile
    const int mtile = blockIdx.y;                   // 64-row tile

    // ---- runtime dtype probe for weight_norm ----
    const float* wnf = (const float*)wn_raw;
    const __half* wnh = (const __half*)wn_raw;
    const float probe = __ldg(wnf);
    const bool norm_f32 = (probe > 6e-5f && probe < 0.06f);

    const int warp_m = wid >> 1;     // 2 x 32 rows
    const int warp_n = wid & 1;      // 2 x 32 cols

    // B ldmatrix per-lane unswizzled bases (two 16-row groups per warp)
    uint32_t brow[2];
    #pragma unroll
    for (int p = 0; p < 2; ++p)
        brow[p] = (uint32_t)((warp_n * 32 + p * 16 + (lid & 15)) * 128 + (lid >> 4) * 16);

    // ---- A cp.async: thread tid copies 4 uint4 chunks per iter (8KB total) ----
    // flat = tid + 128*j ; q = flat>>5 = mi*4+ks (0..15) ; lane = flat&31
    const uint4* abase = g_xa + (size_t)(mtile * 4) * (K / 16) * 32;
    auto cp_a = [&](int it, int slot) {
        uint32_t sdst = sb + SMEM_A + (uint32_t)slot * 8192u + (uint32_t)tid * 16u;
        #pragma unroll
        for (int j = 0; j < 4; ++j) {
            int flat = tid + 128 * j;
            int lane = flat & 31;
            int q = flat >> 5;              // mi*4 + ks
            int mi = q >> 2;
            int ks = q & 3;
            const uint4* src = abase + ((size_t)mi * (K / 16) + it * 4 + ks) * 32 + lane;
            asm volatile("cp.async.cg.shared.global [%0], [%1], 16;"
                         :: "r"(sdst + (uint32_t)j * 2048u), "l"(src) : "memory");
        }
        asm volatile("cp.async.commit_group;" ::: "memory");
    };

    float acc[2][4][4];
    #pragma unroll
    for (int mt = 0; mt < 2; ++mt)
        #pragma unroll
        for (int nt = 0; nt < 4; ++nt)
            #pragma unroll
            for (int e = 0; e < 4; ++e) acc[mt][nt][e] = 0.0f;

    // B staging: 2 groups per thread per iter (64 rows x 4 groups = 256)
    int4  bv[2];
    float bn[2];

    auto ldg_b = [&](int it) {
        #pragma unroll
        for (int i = 0; i < 2; ++i) {
            int gi = tid + 128 * i;
            int br = gi >> 2;
            int bj = gi & 3;
            int gidx = (ntile * 64 + br) * 256 + it * 4 + bj;
            bv[i] = __ldg(wq + gidx);
            bn[i] = norm_f32 ? __ldg(wnf + gidx) : __half2float(__ldg(wnh + gidx));
        }
    };
    auto sts_b = [&](int b) {
        char* bbuf = smem + SMEM_B + b * 8192;
        #pragma unroll
        for (int i = 0; i < 2; ++i) {
            int gi = tid + 128 * i;
            int br = gi >> 2;
            int bj = gi & 3;
            uint32_t o[8];
            dequant16(bv[i], bn[i], o);
            uint32_t off = (uint32_t)(br * 128 + bj * 32);
            *reinterpret_cast<int4*>(bbuf + sw128(off)) =
                make_int4((int)o[0], (int)o[1], (int)o[2], (int)o[3]);
            *reinterpret_cast<int4*>(bbuf + sw128(off + 16)) =
                make_int4((int)o[4], (int)o[5], (int)o[6], (int)o[7]);
        }
    };

    // ---- prologue ----
    ldg_b(0);
    cp_a(0, 0);
    cp_a(1, 1);
    sts_b(0);
    asm volatile("cp.async.wait_group 1;" ::: "memory");   // slot 0 ready
    __syncthreads();

    #pragma unroll 1
    for (int it = 0; it < KITERS; ++it) {
        const int b = it & 1;
        if (it + 1 < KITERS) ldg_b(it + 1);

        const char* aslot = smem + SMEM_A + (it % 3) * 8192;
        const uint32_t bb = sb + SMEM_B + (uint32_t)b * 8192u;

        #pragma unroll
        for (int ks = 0; ks < 4; ++ks) {
            const uint32_t kb = (uint32_t)(ks * 32);   // 16 halves per k-step

            // A fragments for this ks: 2 x LDS.128
            uint4 af[2];
            #pragma unroll
            for (int mt = 0; mt < 2; ++mt)
                af[mt] = *reinterpret_cast<const uint4*>(
                    aslot + (((warp_m * 2 + mt) * 4 + ks) * 32 + lid) * 16);

            uint32_t bf[2][4];
            #pragma unroll
            for (int p = 0; p < 2; ++p) {
                uint32_t addr = bb + sw128(brow[p] + kb);
                asm volatile(
                    "ldmatrix.sync.aligned.m8n8.x4.shared.b16 {%0,%1,%2,%3}, [%4];"
                    : "=r"(bf[p][0]), "=r"(bf[p][1]), "=r"(bf[p][2]), "=r"(bf[p][3])
                    : "r"(addr));
            }
            #pragma unroll
            for (int mt = 0; mt < 2; ++mt) {
                #pragma unroll
                for (int nt = 0; nt < 4; ++nt) {
                    uint32_t b0 = bf[nt >> 1][nt & 1];
                    uint32_t b1 = bf[nt >> 1][(nt & 1) + 2];
                    asm volatile(
                        "mma.sync.aligned.m16n8k16.row.col.f32.f16.f16.f32 "
                        "{%0,%1,%2,%3}, {%4,%5,%6,%7}, {%8,%9}, {%0,%1,%2,%3};"
                        : "+f"(acc[mt][nt][0]), "+f"(acc[mt][nt][1]),
                          "+f"(acc[mt][nt][2]), "+f"(acc[mt][nt][3])
                        : "r"(af[mt].x), "r"(af[mt].y),
                          "r"(af[mt].z), "r"(af[mt].w),
                          "r"(b0), "r"(b1));
                }
            }
        }

        if (it + 1 < KITERS) sts_b(b ^ 1);

        // Issue A copy for it+2 (clamped at tail; slot clobber is safe:
        // (it+2)%3 == (it-1)%3 which was already consumed).
        int itp = it + 2 < KITERS ? it + 2 : KITERS - 1;
        cp_a(itp, (it + 2) % 3);
        asm volatile("cp.async.wait_group 1;" ::: "memory");   // slot (it+1) ready
        __syncthreads();
    }

    // ---- epilogue: write accumulators + bias ----
    {
        const int mbase = mtile * 64 + warp_m * 32;
        const int nbase = ntile * 64 + warp_n * 32;
        const int rq = lid >> 2;             // row within m16 (0..7)
        const int cq = (lid & 3) * 2;        // col within n8 (0,2,4,6)
        #pragma unroll
        for (int mt = 0; mt < 2; ++mt) {
            #pragma unroll
            for (int nt = 0; nt < 4; ++nt) {
                int m0 = mbase + mt * 16 + rq;
                int n0 = nbase + nt * 8 + cq;
                float2 bsv = __ldg(reinterpret_cast<const float2*>(bias + n0));
                float2 v0, v1;
                v0.x = acc[mt][nt][0] + bsv.x;
                v0.y = acc[mt][nt][1] + bsv.y;
                v1.x = acc[mt][nt][2] + bsv.x;
                v1.y = acc[mt][nt][3] + bsv.y;
                *reinterpret_cast<float2*>(out + (size_t)m0 * N + n0) = v0;
                *reinterpret_cast<float2*>(out + (size_t)(m0 + 8) * N + n0) = v1;
            }
        }
    }
}

// ---------------- launch ----------------

extern "C" void kernel_launch(void* const* d_in, const int* in_sizes, int n_in,
                              void* d_out, int out_size) {
    (void)in_sizes; (void)n_in; (void)out_size;
    const float* x    = (const float*)d_in[0];
    const int4*  wq   = (const int4*)d_in[1];    // [NUM_GROUPS] groups of 4 int32
    const void*  wn   = (const void*)d_in[2];    // [NUM_GROUPS] norms
    const float* bias = (const float*)d_in[3];
    float*       out  = (float*)d_out;

    cudaFuncSetAttribute(linear2bit_gemm,
                         cudaFuncAttributeMaxDynamicSharedMemorySize, SMEM_TOTAL);

    convert_x_frag<<<(M / 16) * (K / 16) * 32 / 256, 256>>>(x);
    linear2bit_gemm<<<dim3(N / 64, M / 64), 128, SMEM_TOTAL>>>(wq, wn, bias, out);
}

// round 7
// speedup vs baseline: 1.0468x; 1.0468x over previous
#include <cuda_runtime.h>
#include <cuda_fp16.h>
#include <cstdint>

// Problem dims
static constexpr int M = 256;
static constexpr int K = 4096;
static constexpr int N = 8192;
static constexpr int KHALF = K / 2;          // 2048 per split-K slice
static constexpr int KITERS = KHALF / 64;    // 32 K-chunks of 64 per CTA

// SMEM layout (per 256-thread CTA, tile 128x64):
//  [0,1024)            header (unused, alignment)
//  [1024, +3*16384)    A fragment ring: 3 stages x 16KB (8 mi x 4 ks x 32 lanes x 16B)
//  [50176, +2*8192)    B dequant double buffer (64 rows x 128B each)
static constexpr int SMEM_A = 1024;
static constexpr int SMEM_B = 1024 + 3 * 16384;      // 50176
static constexpr int SMEM_TOTAL = SMEM_B + 2 * 8192; // 66560

// A in m16n8k16 fragment layout, fp16, built by convert kernel.
// Index: ((mi * (K/16) + ki) * 32 + lane) -> uint4 (regs a0,a1,a2,a3)
__device__ uint4 g_xa[(M / 16) * (K / 16) * 32];

// ---------------- helpers ----------------

__device__ __forceinline__ uint32_t smem_u32(const void* p) {
    uint32_t a;
    asm("{ .reg .u64 t; cvta.to.shared.u64 t, %1; cvt.u32.u64 %0, t; }"
        : "=r"(a) : "l"(p));
    return a;
}

__device__ __forceinline__ uint32_t sw128(uint32_t off) {
    return off ^ ((off >> 3) & 0x70);
}

// Dequant one 16-weight group (4 int32, low byte each = 4 x 2-bit codes)
// into 8 u32 = 16 fp16, via a 4-entry fp16 LUT + PRMT byte gather.
__device__ __forceinline__ void dequant16(const int4& p4, float n, uint32_t o[8]) {
    uint32_t b1 = (uint32_t)__half_as_ushort(__float2half_rn(n));
    uint32_t b3 = (uint32_t)__half_as_ushort(__float2half_rn(n * (1.0f / 3.0f)));
    uint32_t loT = (b1 ^ 0x8000u) | ((b3 ^ 0x8000u) << 16);  // bytes: [-n][-n/3]
    uint32_t hiT = b3 | (b1 << 16);                          // bytes: [n/3][n]
    uint32_t pv[4] = { (uint32_t)p4.x, (uint32_t)p4.y, (uint32_t)p4.z, (uint32_t)p4.w };
    #pragma unroll
    for (int q = 0; q < 4; ++q) {
        uint32_t by = pv[q] & 0xFFu;   // 4 x 2-bit codes
        uint32_t l = by & 0xFu;
        uint32_t h = by >> 4;
        uint32_t c0 = (l & 3u) * 0x22u + (l & 0xCu) * 0x880u + 0x1010u;
        uint32_t c1 = (h & 3u) * 0x22u + (h & 0xCu) * 0x880u + 0x1010u;
        o[2 * q]     = __byte_perm(loT, hiT, c0);
        o[2 * q + 1] = __byte_perm(loT, hiT, c1);
    }
}

// ---------------- kernel 0: x fp32 -> A-fragment fp16 layout ----------------

__global__ void convert_x_frag(const float* __restrict__ x) {
    int g = blockIdx.x * blockDim.x + threadIdx.x;   // 0 .. 131071
    int lane = g & 31;
    int ki = (g >> 5) & (K / 16 - 1);
    int mi = g >> 13;
    int r = lane >> 2;
    int c = (lane & 3) * 2;
    const float* base = x + (size_t)(mi * 16 + r) * K + ki * 16 + c;
    float2 v00 = *reinterpret_cast<const float2*>(base);
    float2 v10 = *reinterpret_cast<const float2*>(base + 8 * K);
    float2 v01 = *reinterpret_cast<const float2*>(base + 8);
    float2 v11 = *reinterpret_cast<const float2*>(base + 8 * K + 8);
    uint4 o;
    o.x = (uint32_t)__half_as_ushort(__float2half_rn(v00.x)) |
          ((uint32_t)__half_as_ushort(__float2half_rn(v00.y)) << 16);
    o.y = (uint32_t)__half_as_ushort(__float2half_rn(v10.x)) |
          ((uint32_t)__half_as_ushort(__float2half_rn(v10.y)) << 16);
    o.z = (uint32_t)__half_as_ushort(__float2half_rn(v01.x)) |
          ((uint32_t)__half_as_ushort(__float2half_rn(v01.y)) << 16);
    o.w = (uint32_t)__half_as_ushort(__float2half_rn(v11.x)) |
          ((uint32_t)__half_as_ushort(__float2half_rn(v11.y)) << 16);
    g_xa[g] = o;
}

// ---------------- kernel 0b: zero the output ----------------

__global__ void zero_out_kernel(float* __restrict__ out) {
    int i = blockIdx.x * blockDim.x + threadIdx.x;   // float4 index
    reinterpret_cast<float4*>(out)[i] = make_float4(0.f, 0.f, 0.f, 0.f);
}

// ---------------- kernel 1: fused dequant + fp16 HMMA GEMM, split-K=2 ----------
// Grid (128, 2, 2): x = N-tile (64 cols), y = M-tile (128 rows), z = K-half.
// 256 threads = 8 warps as 4(M) x 2(N); warp tile 32x32.
// A: cp.async gmem->SMEM ring (3 stages, issued 2 iters ahead), LDS.128 per ks.
// B: packed LDG 1 iter ahead -> dequant -> SMEM (SW128) -> ldmatrix, 2 buffers.
// Epilogue: red.global.add.f32 into pre-zeroed out (2 contributors/element).

__global__ void __launch_bounds__(256, 3)
linear2bit_gemm(const int4* __restrict__ wq,        // one int4 = one 16-value group
                const void* __restrict__ wn_raw,    // [NUM_GROUPS] norms (fp32 or fp16)
                const float* __restrict__ bias,     // [N]
                float* __restrict__ out)            // [M, N]
{
    extern __shared__ char smem[];
    const uint32_t sb = smem_u32(smem);
    const int tid = threadIdx.x;
    const int wid = tid >> 5;
    const int lid = tid & 31;
    const int ntile = blockIdx.x;                   // 64-col tile
    const int mtile = blockIdx.y;                   // 128-row tile
    const int kz    = blockIdx.z;                   // K-half

    // ---- runtime dtype probe for weight_norm ----
    const float* wnf = (const float*)wn_raw;
    const __half* wnh = (const __half*)wn_raw;
    const float probe = __ldg(wnf);
    const bool norm_f32 = (probe > 6e-5f && probe < 0.06f);

    const int warp_m = wid >> 1;     // 4 x 32 rows
    const int warp_n = wid & 1;      // 2 x 32 cols

    // B ldmatrix per-lane unswizzled bases (two 16-row groups per warp)
    uint32_t brow[2];
    #pragma unroll
    for (int p = 0; p < 2; ++p)
        brow[p] = (uint32_t)((warp_n * 32 + p * 16 + (lid & 15)) * 128 + (lid >> 4) * 16);

    // ---- A cp.async: thread tid copies 4 uint4 chunks per iter (16KB) ----
    // flat = tid + 256*j ; q = flat>>5 = mi*4+ks ; lane = flat&31
    // ki = kz*(KHALF/16) + it*4 + ks
    const uint4* abase = g_xa + (size_t)(mtile * 8) * (K / 16) * 32
                              + (size_t)(kz * (KHALF / 16)) * 32;
    auto cp_a = [&](int it, int slot) {
        uint32_t sdst = sb + SMEM_A + (uint32_t)slot * 16384u + (uint32_t)tid * 16u;
        #pragma unroll
        for (int j = 0; j < 4; ++j) {
            int flat = tid + 256 * j;
            int lane = flat & 31;
            int q = flat >> 5;              // mi*4 + ks
            int mi = q >> 2;
            int ks = q & 3;
            const uint4* src = abase + ((size_t)mi * (K / 16) + it * 4 + ks) * 32 + lane;
            asm volatile("cp.async.cg.shared.global [%0], [%1], 16;"
                         :: "r"(sdst + (uint32_t)j * 4096u), "l"(src) : "memory");
        }
        asm volatile("cp.async.commit_group;" ::: "memory");
    };

    // A LDS byte base within a slot for this warp/lane
    const uint32_t a_lds_off = (uint32_t)((warp_m * 2 * 4) * 32 + lid) * 16u;

    float acc[2][4][4];
    #pragma unroll
    for (int mt = 0; mt < 2; ++mt)
        #pragma unroll
        for (int nt = 0; nt < 4; ++nt)
            #pragma unroll
            for (int e = 0; e < 4; ++e) acc[mt][nt][e] = 0.0f;

    // B staging: 1 group per thread per iter (64 rows x 4 groups = 256)
    const int br = tid >> 2;        // B row in tile (0..63)
    const int bj = tid & 3;         // group within K-chunk (0..3)
    const int bg_base = (ntile * 64 + br) * 256 + kz * (KHALF / 16) + bj;   // + it*4

    int4  bv;
    float bn;

    auto ldg_b = [&](int it) {
        int gidx = bg_base + it * 4;
        bv = __ldg(wq + gidx);
        bn = norm_f32 ? __ldg(wnf + gidx) : __half2float(__ldg(wnh + gidx));
    };
    auto sts_b = [&](int b) {
        char* bbuf = smem + SMEM_B + b * 8192;
        uint32_t o[8];
        dequant16(bv, bn, o);
        uint32_t off = (uint32_t)(br * 128 + bj * 32);
        *reinterpret_cast<int4*>(bbuf + sw128(off)) =
            make_int4((int)o[0], (int)o[1], (int)o[2], (int)o[3]);
        *reinterpret_cast<int4*>(bbuf + sw128(off + 16)) =
            make_int4((int)o[4], (int)o[5], (int)o[6], (int)o[7]);
    };

    // ---- prologue ----
    ldg_b(0);
    cp_a(0, 0);
    cp_a(1, 1);
    sts_b(0);
    asm volatile("cp.async.wait_group 1;" ::: "memory");   // slot 0 ready
    __syncthreads();

    #pragma unroll 1
    for (int it = 0; it < KITERS; ++it) {
        const int b = it & 1;
        if (it + 1 < KITERS) ldg_b(it + 1);

        const char* aslot = smem + SMEM_A + (it % 3) * 16384 + a_lds_off;
        const uint32_t bb = sb + SMEM_B + (uint32_t)b * 8192u;

        #pragma unroll
        for (int ks = 0; ks < 4; ++ks) {
            const uint32_t kb = (uint32_t)(ks * 32);   // 16 halves per k-step

            // A fragments for this ks: 2 x LDS.128
            uint4 af[2];
            #pragma unroll
            for (int mt = 0; mt < 2; ++mt)
                af[mt] = *reinterpret_cast<const uint4*>(
                    aslot + (mt * 4 + ks) * 32 * 16);

            uint32_t bf[2][4];
            #pragma unroll
            for (int p = 0; p < 2; ++p) {
                uint32_t addr = bb + sw128(brow[p] + kb);
                asm volatile(
                    "ldmatrix.sync.aligned.m8n8.x4.shared.b16 {%0,%1,%2,%3}, [%4];"
                    : "=r"(bf[p][0]), "=r"(bf[p][1]), "=r"(bf[p][2]), "=r"(bf[p][3])
                    : "r"(addr));
            }
            #pragma unroll
            for (int mt = 0; mt < 2; ++mt) {
                #pragma unroll
                for (int nt = 0; nt < 4; ++nt) {
                    uint32_t b0 = bf[nt >> 1][nt & 1];
                    uint32_t b1 = bf[nt >> 1][(nt & 1) + 2];
                    asm volatile(
                        "mma.sync.aligned.m16n8k16.row.col.f32.f16.f16.f32 "
                        "{%0,%1,%2,%3}, {%4,%5,%6,%7}, {%8,%9}, {%0,%1,%2,%3};"
                        : "+f"(acc[mt][nt][0]), "+f"(acc[mt][nt][1]),
                          "+f"(acc[mt][nt][2]), "+f"(acc[mt][nt][3])
                        : "r"(af[mt].x), "r"(af[mt].y),
                          "r"(af[mt].z), "r"(af[mt].w),
                          "r"(b0), "r"(b1));
                }
            }
        }

        if (it + 1 < KITERS) sts_b(b ^ 1);

        // Issue A copy for it+2 (clamped at tail; slot clobber is safe:
        // (it+2)%3 == (it-1)%3 which was already consumed).
        int itp = it + 2 < KITERS ? it + 2 : KITERS - 1;
        cp_a(itp, (it + 2) % 3);
        asm volatile("cp.async.wait_group 1;" ::: "memory");   // slot (it+1) ready
        __syncthreads();
    }

    // ---- epilogue: red.global.add accumulators (+ bias on kz==0 half) ----
    {
        const int mbase = mtile * 128 + warp_m * 32;
        const int nbase = ntile * 64 + warp_n * 32;
        const int rq = lid >> 2;             // row within m16 (0..7)
        const int cq = (lid & 3) * 2;        // col within n8 (0,2,4,6)
        const bool add_bias = (kz == 0);
        #pragma unroll
        for (int mt = 0; mt < 2; ++mt) {
            #pragma unroll
            for (int nt = 0; nt < 4; ++nt) {
                int m0 = mbase + mt * 16 + rq;
                int n0 = nbase + nt * 8 + cq;
                float bx = 0.f, by = 0.f;
                if (add_bias) {
                    float2 bsv = __ldg(reinterpret_cast<const float2*>(bias + n0));
                    bx = bsv.x; by = bsv.y;
                }
                float* p0 = out + (size_t)m0 * N + n0;
                float* p1 = out + (size_t)(m0 + 8) * N + n0;
                asm volatile("red.global.add.f32 [%0], %1;" :: "l"(p0),     "f"(acc[mt][nt][0] + bx) : "memory");
                asm volatile("red.global.add.f32 [%0], %1;" :: "l"(p0 + 1), "f"(acc[mt][nt][1] + by) : "memory");
                asm volatile("red.global.add.f32 [%0], %1;" :: "l"(p1),     "f"(acc[mt][nt][2] + bx) : "memory");
                asm volatile("red.global.add.f32 [%0], %1;" :: "l"(p1 + 1), "f"(acc[mt][nt][3] + by) : "memory");
            }
        }
    }
}

// ---------------- launch ----------------

extern "C" void kernel_launch(void* const* d_in, const int* in_sizes, int n_in,
                              void* d_out, int out_size) {
    (void)in_sizes; (void)n_in; (void)out_size;
    const float* x    = (const float*)d_in[0];
    const int4*  wq   = (const int4*)d_in[1];    // [NUM_GROUPS] groups of 4 int32
    const void*  wn   = (const void*)d_in[2];    // [NUM_GROUPS] norms
    const float* bias = (const float*)d_in[3];
    float*       out  = (float*)d_out;

    cudaFuncSetAttribute(linear2bit_gemm,
                         cudaFuncAttributeMaxDynamicSharedMemorySize, SMEM_TOTAL);

    convert_x_frag<<<(M / 16) * (K / 16) * 32 / 256, 256>>>(x);
    zero_out_kernel<<<(M * N / 4) / 256, 256>>>(out);
    linear2bit_gemm<<<dim3(N / 64, M / 128, 2), 256, SMEM_TOTAL>>>(wq, wn, bias, out);
}

// round 8
// speedup vs baseline: 1.1665x; 1.1143x over previous
#include <cuda_runtime.h>
#include <cuda_fp16.h>
#include <cstdint>

// Problem dims
static constexpr int M = 256;
static constexpr int K = 4096;
static constexpr int N = 8192;
static constexpr int KITERS = K / 64;     // 64 K-chunks of 64

// SMEM layout (per 256-thread CTA, tile 128x64):
//  [0,1024)            header (unused, alignment)
//  [1024, +3*16384)    A fragment ring: 3 stages x 16KB (8 mi x 4 ks x 32 lanes x 16B)
//  [50176, +2*8192)    B dequant double buffer (64 rows x 128B each)
static constexpr int SMEM_A = 1024;
static constexpr int SMEM_B = 1024 + 3 * 16384;      // 50176
static constexpr int SMEM_TOTAL = SMEM_B + 2 * 8192; // 66560

// A in m16n8k16 fragment layout, fp16, built by convert kernel.
// Index: ((mi * (K/16) + ki) * 32 + lane) -> uint4 (regs a0,a1,a2,a3)
__device__ uint4 g_xa[(M / 16) * (K / 16) * 32];

// ---------------- helpers ----------------

__device__ __forceinline__ uint32_t smem_u32(const void* p) {
    uint32_t a;
    asm("{ .reg .u64 t; cvta.to.shared.u64 t, %1; cvt.u32.u64 %0, t; }"
        : "=r"(a) : "l"(p));
    return a;
}

__device__ __forceinline__ uint32_t sw128(uint32_t off) {
    return off ^ ((off >> 3) & 0x70);
}

// Dequant one 16-weight group (4 int32, low byte each = 4 x 2-bit codes)
// into 8 u32 = 16 fp16, via a 4-entry fp16 LUT + PRMT byte gather.
__device__ __forceinline__ void dequant16(const int4& p4, float n, uint32_t o[8]) {
    uint32_t b1 = (uint32_t)__half_as_ushort(__float2half_rn(n));
    uint32_t b3 = (uint32_t)__half_as_ushort(__float2half_rn(n * (1.0f / 3.0f)));
    uint32_t loT = (b1 ^ 0x8000u) | ((b3 ^ 0x8000u) << 16);  // bytes: [-n][-n/3]
    uint32_t hiT = b3 | (b1 << 16);                          // bytes: [n/3][n]
    uint32_t pv[4] = { (uint32_t)p4.x, (uint32_t)p4.y, (uint32_t)p4.z, (uint32_t)p4.w };
    #pragma unroll
    for (int q = 0; q < 4; ++q) {
        uint32_t by = pv[q] & 0xFFu;   // 4 x 2-bit codes
        uint32_t l = by & 0xFu;
        uint32_t h = by >> 4;
        uint32_t c0 = (l & 3u) * 0x22u + (l & 0xCu) * 0x880u + 0x1010u;
        uint32_t c1 = (h & 3u) * 0x22u + (h & 0xCu) * 0x880u + 0x1010u;
        o[2 * q]     = __byte_perm(loT, hiT, c0);
        o[2 * q + 1] = __byte_perm(loT, hiT, c1);
    }
}

// ---------------- kernel 0: x fp32 -> A-fragment fp16 layout ----------------

__global__ void convert_x_frag(const float* __restrict__ x) {
    int g = blockIdx.x * blockDim.x + threadIdx.x;   // 0 .. 131071
    int lane = g & 31;
    int ki = (g >> 5) & (K / 16 - 1);
    int mi = g >> 13;
    int r = lane >> 2;
    int c = (lane & 3) * 2;
    const float* base = x + (size_t)(mi * 16 + r) * K + ki * 16 + c;
    float2 v00 = *reinterpret_cast<const float2*>(base);
    float2 v10 = *reinterpret_cast<const float2*>(base + 8 * K);
    float2 v01 = *reinterpret_cast<const float2*>(base + 8);
    float2 v11 = *reinterpret_cast<const float2*>(base + 8 * K + 8);
    uint4 o;
    o.x = (uint32_t)__half_as_ushort(__float2half_rn(v00.x)) |
          ((uint32_t)__half_as_ushort(__float2half_rn(v00.y)) << 16);
    o.y = (uint32_t)__half_as_ushort(__float2half_rn(v10.x)) |
          ((uint32_t)__half_as_ushort(__float2half_rn(v10.y)) << 16);
    o.z = (uint32_t)__half_as_ushort(__float2half_rn(v01.x)) |
          ((uint32_t)__half_as_ushort(__float2half_rn(v01.y)) << 16);
    o.w = (uint32_t)__half_as_ushort(__float2half_rn(v11.x)) |
          ((uint32_t)__half_as_ushort(__float2half_rn(v11.y)) << 16);
    g_xa[g] = o;
}

// ---------------- kernel 1: fused dequant + fp16 HMMA GEMM ----------------
// Grid (128, 2): blockIdx.x = N-tile (64 cols), blockIdx.y = M-tile (128 rows)
// 256 threads = 8 warps as 4(M) x 2(N); warp tile 32x32.
// A: cp.async gmem->SMEM ring (3 stages, issued 2 iters ahead).
// B: packed LDG 1 iter ahead -> dequant -> SMEM (SW128) -> ldmatrix, 2 buffers.
// NEW: fragment registers double-buffered across ks — loads for ks+1 issue
// before the MMAs of ks, hiding LDS/LDSM latency behind tensor work.

__global__ void __launch_bounds__(256, 2)
linear2bit_gemm(const int4* __restrict__ wq,        // one int4 = one 16-value group
                const void* __restrict__ wn_raw,    // [NUM_GROUPS] norms (fp32 or fp16)
                const float* __restrict__ bias,     // [N]
                float* __restrict__ out)            // [M, N]
{
    extern __shared__ char smem[];
    const uint32_t sb = smem_u32(smem);
    const int tid = threadIdx.x;
    const int wid = tid >> 5;
    const int lid = tid & 31;
    const int ntile = blockIdx.x;                   // 64-col tile
    const int mtile = blockIdx.y;                   // 128-row tile

    // ---- runtime dtype probe for weight_norm ----
    const float* wnf = (const float*)wn_raw;
    const __half* wnh = (const __half*)wn_raw;
    const float probe = __ldg(wnf);
    const bool norm_f32 = (probe > 6e-5f && probe < 0.06f);

    const int warp_m = wid >> 1;     // 4 x 32 rows
    const int warp_n = wid & 1;      // 2 x 32 cols

    // B ldmatrix per-lane unswizzled bases (two 16-row groups per warp)
    uint32_t brow[2];
    #pragma unroll
    for (int p = 0; p < 2; ++p)
        brow[p] = (uint32_t)((warp_n * 32 + p * 16 + (lid & 15)) * 128 + (lid >> 4) * 16);

    // ---- A cp.async: thread tid copies 4 uint4 chunks per iter (16KB) ----
    const uint4* abase = g_xa + (size_t)(mtile * 8) * (K / 16) * 32;
    auto cp_a = [&](int it, int slot) {
        uint32_t sdst = sb + SMEM_A + (uint32_t)slot * 16384u + (uint32_t)tid * 16u;
        #pragma unroll
        for (int j = 0; j < 4; ++j) {
            int flat = tid + 256 * j;
            int lane = flat & 31;
            int q = flat >> 5;              // mi*4 + ks
            int mi = q >> 2;
            int ks = q & 3;
            const uint4* src = abase + ((size_t)mi * (K / 16) + it * 4 + ks) * 32 + lane;
            asm volatile("cp.async.cg.shared.global [%0], [%1], 16;"
                         :: "r"(sdst + (uint32_t)j * 4096u), "l"(src) : "memory");
        }
        asm volatile("cp.async.commit_group;" ::: "memory");
    };

    // A LDS byte base within a slot for this warp/lane
    const uint32_t a_lds_off = (uint32_t)((warp_m * 2 * 4) * 32 + lid) * 16u;

    float acc[2][4][4];
    #pragma unroll
    for (int mt = 0; mt < 2; ++mt)
        #pragma unroll
        for (int nt = 0; nt < 4; ++nt)
            #pragma unroll
            for (int e = 0; e < 4; ++e) acc[mt][nt][e] = 0.0f;

    // B staging: 1 group per thread per iter (64 rows x 4 groups = 256)
    const int br = tid >> 2;        // B row in tile (0..63)
    const int bj = tid & 3;         // group within K-chunk (0..3)
    const int bg_base = (ntile * 64 + br) * 256 + bj;   // + it*4

    int4  bv;
    float bn;

    auto ldg_b = [&](int it) {
        int gidx = bg_base + it * 4;
        bv = __ldg(wq + gidx);
        bn = norm_f32 ? __ldg(wnf + gidx) : __half2float(__ldg(wnh + gidx));
    };
    auto sts_b = [&](int b) {
        char* bbuf = smem + SMEM_B + b * 8192;
        uint32_t o[8];
        dequant16(bv, bn, o);
        uint32_t off = (uint32_t)(br * 128 + bj * 32);
        *reinterpret_cast<int4*>(bbuf + sw128(off)) =
            make_int4((int)o[0], (int)o[1], (int)o[2], (int)o[3]);
        *reinterpret_cast<int4*>(bbuf + sw128(off + 16)) =
            make_int4((int)o[4], (int)o[5], (int)o[6], (int)o[7]);
    };

    // ---- fragment load helpers (ks-indexed) ----
    auto load_a = [&](const char* aslot, int ks, uint4 af[2]) {
        #pragma unroll
        for (int mt = 0; mt < 2; ++mt)
            af[mt] = *reinterpret_cast<const uint4*>(
                aslot + (mt * 4 + ks) * 32 * 16);
    };
    auto load_b = [&](uint32_t bb, int ks, uint32_t bf[2][4]) {
        const uint32_t kb = (uint32_t)(ks * 32);
        #pragma unroll
        for (int p = 0; p < 2; ++p) {
            uint32_t addr = bb + sw128(brow[p] + kb);
            asm volatile(
                "ldmatrix.sync.aligned.m8n8.x4.shared.b16 {%0,%1,%2,%3}, [%4];"
                : "=r"(bf[p][0]), "=r"(bf[p][1]), "=r"(bf[p][2]), "=r"(bf[p][3])
                : "r"(addr));
        }
    };

    // ---- prologue ----
    ldg_b(0);
    cp_a(0, 0);
    cp_a(1, 1);
    sts_b(0);
    asm volatile("cp.async.wait_group 1;" ::: "memory");   // slot 0 ready
    __syncthreads();

    #pragma unroll 1
    for (int it = 0; it < KITERS; ++it) {
        const int b = it & 1;
        if (it + 1 < KITERS) ldg_b(it + 1);

        const char* aslot = smem + SMEM_A + (it % 3) * 16384 + a_lds_off;
        const uint32_t bb = sb + SMEM_B + (uint32_t)b * 8192u;

        // two-stage register pipeline over ks
        uint4    af0[2], af1[2];
        uint32_t bf0[2][4], bf1[2][4];
        load_a(aslot, 0, af0);
        load_b(bb, 0, bf0);

        #pragma unroll
        for (int ks = 0; ks < 4; ++ks) {
            // prefetch ks+1 fragments before issuing MMAs for ks
            if (ks < 3) {
                load_a(aslot, ks + 1, af1);
                load_b(bb, ks + 1, bf1);
            }
            #pragma unroll
            for (int mt = 0; mt < 2; ++mt) {
                #pragma unroll
                for (int nt = 0; nt < 4; ++nt) {
                    uint32_t b0 = bf0[nt >> 1][nt & 1];
                    uint32_t b1 = bf0[nt >> 1][(nt & 1) + 2];
                    asm volatile(
                        "mma.sync.aligned.m16n8k16.row.col.f32.f16.f16.f32 "
                        "{%0,%1,%2,%3}, {%4,%5,%6,%7}, {%8,%9}, {%0,%1,%2,%3};"
                        : "+f"(acc[mt][nt][0]), "+f"(acc[mt][nt][1]),
                          "+f"(acc[mt][nt][2]), "+f"(acc[mt][nt][3])
                        : "r"(af0[mt].x), "r"(af0[mt].y),
                          "r"(af0[mt].z), "r"(af0[mt].w),
                          "r"(b0), "r"(b1));
                }
            }
            // rotate pipeline registers
            if (ks < 3) {
                #pragma unroll
                for (int mt = 0; mt < 2; ++mt) af0[mt] = af1[mt];
                #pragma unroll
                for (int p = 0; p < 2; ++p)
                    #pragma unroll
                    for (int e = 0; e < 4; ++e) bf0[p][e] = bf1[p][e];
            }
        }

        if (it + 1 < KITERS) sts_b(b ^ 1);

        // Issue A copy for it+2 (clamped at tail; slot clobber is safe:
        // (it+2)%3 == (it-1)%3 which was already consumed).
        int itp = it + 2 < KITERS ? it + 2 : KITERS - 1;
        cp_a(itp, (it + 2) % 3);
        asm volatile("cp.async.wait_group 1;" ::: "memory");   // slot (it+1) ready
        __syncthreads();
    }

    // ---- epilogue: write accumulators + bias ----
    {
        const int mbase = mtile * 128 + warp_m * 32;
        const int nbase = ntile * 64 + warp_n * 32;
        const int rq = lid >> 2;             // row within m16 (0..7)
        const int cq = (lid & 3) * 2;        // col within n8 (0,2,4,6)
        #pragma unroll
        for (int mt = 0; mt < 2; ++mt) {
            #pragma unroll
            for (int nt = 0; nt < 4; ++nt) {
                int m0 = mbase + mt * 16 + rq;
                int n0 = nbase + nt * 8 + cq;
                float2 bsv = __ldg(reinterpret_cast<const float2*>(bias + n0));
                float2 v0, v1;
                v0.x = acc[mt][nt][0] + bsv.x;
                v0.y = acc[mt][nt][1] + bsv.y;
                v1.x = acc[mt][nt][2] + bsv.x;
                v1.y = acc[mt][nt][3] + bsv.y;
                *reinterpret_cast<float2*>(out + (size_t)m0 * N + n0) = v0;
                *reinterpret_cast<float2*>(out + (size_t)(m0 + 8) * N + n0) = v1;
            }
        }
    }
}

// ---------------- launch ----------------

extern "C" void kernel_launch(void* const* d_in, const int* in_sizes, int n_in,
                              void* d_out, int out_size) {
    (void)in_sizes; (void)n_in; (void)out_size;
    const float* x    = (const float*)d_in[0];
    const int4*  wq   = (const int4*)d_in[1];    // [NUM_GROUPS] groups of 4 int32
    const void*  wn   = (const void*)d_in[2];    // [NUM_GROUPS] norms
    const float* bias = (const float*)d_in[3];
    float*       out  = (float*)d_out;

    cudaFuncSetAttribute(linear2bit_gemm,
                         cudaFuncAttributeMaxDynamicSharedMemorySize, SMEM_TOTAL);

    convert_x_frag<<<(M / 16) * (K / 16) * 32 / 256, 256>>>(x);
    linear2bit_gemm<<<dim3(N / 64, M / 128), 256, SMEM_TOTAL>>>(wq, wn, bias, out);
}

// round 9
// speedup vs baseline: 1.2093x; 1.0367x over previous
#include <cuda_runtime.h>
#include <cuda_fp16.h>
#include <cstdint>

// Problem dims
static constexpr int M = 256;
static constexpr int K = 4096;
static constexpr int N = 8192;
static constexpr int KITERS = K / 64;     // 64 K-chunks of 64

// SMEM layout (per 256-thread CTA, tile 256x64):
//  [0,1024)             header (unused, alignment)
//  [1024, +3*32768)     A fragment ring: 3 stages x 32KB (16 mi x 4 ks x 32 lanes x 16B)
//  [99328, +2*8192)     B dequant double buffer (64 rows x 128B each)
static constexpr int SMEM_A = 1024;
static constexpr int SMEM_B = 1024 + 3 * 32768;       // 99328
static constexpr int SMEM_TOTAL = SMEM_B + 2 * 8192;  // 115712

// A in m16n8k16 fragment layout, fp16, built by convert kernel.
// Index: ((mi * (K/16) + ki) * 32 + lane) -> uint4 (regs a0,a1,a2,a3)
__device__ uint4 g_xa[(M / 16) * (K / 16) * 32];

// ---------------- helpers ----------------

__device__ __forceinline__ uint32_t smem_u32(const void* p) {
    uint32_t a;
    asm("{ .reg .u64 t; cvta.to.shared.u64 t, %1; cvt.u32.u64 %0, t; }"
        : "=r"(a) : "l"(p));
    return a;
}

__device__ __forceinline__ uint32_t sw128(uint32_t off) {
    return off ^ ((off >> 3) & 0x70);
}

// Dequant one 16-weight group (4 int32, low byte each = 4 x 2-bit codes)
// into 8 u32 = 16 fp16, via a 4-entry fp16 LUT + PRMT byte gather.
__device__ __forceinline__ void dequant16(const int4& p4, float n, uint32_t o[8]) {
    uint32_t b1 = (uint32_t)__half_as_ushort(__float2half_rn(n));
    uint32_t b3 = (uint32_t)__half_as_ushort(__float2half_rn(n * (1.0f / 3.0f)));
    uint32_t loT = (b1 ^ 0x8000u) | ((b3 ^ 0x8000u) << 16);  // bytes: [-n][-n/3]
    uint32_t hiT = b3 | (b1 << 16);                          // bytes: [n/3][n]
    uint32_t pv[4] = { (uint32_t)p4.x, (uint32_t)p4.y, (uint32_t)p4.z, (uint32_t)p4.w };
    #pragma unroll
    for (int q = 0; q < 4; ++q) {
        uint32_t by = pv[q] & 0xFFu;   // 4 x 2-bit codes
        uint32_t l = by & 0xFu;
        uint32_t h = by >> 4;
        uint32_t c0 = (l & 3u) * 0x22u + (l & 0xCu) * 0x880u + 0x1010u;
        uint32_t c1 = (h & 3u) * 0x22u + (h & 0xCu) * 0x880u + 0x1010u;
        o[2 * q]     = __byte_perm(loT, hiT, c0);
        o[2 * q + 1] = __byte_perm(loT, hiT, c1);
    }
}

// ---------------- kernel 0: x fp32 -> A-fragment fp16 layout ----------------

__global__ void convert_x_frag(const float* __restrict__ x) {
    int g = blockIdx.x * blockDim.x + threadIdx.x;   // 0 .. 131071
    int lane = g & 31;
    int ki = (g >> 5) & (K / 16 - 1);
    int mi = g >> 13;
    int r = lane >> 2;
    int c = (lane & 3) * 2;
    const float* base = x + (size_t)(mi * 16 + r) * K + ki * 16 + c;
    float2 v00 = *reinterpret_cast<const float2*>(base);
    float2 v10 = *reinterpret_cast<const float2*>(base + 8 * K);
    float2 v01 = *reinterpret_cast<const float2*>(base + 8);
    float2 v11 = *reinterpret_cast<const float2*>(base + 8 * K + 8);
    uint4 o;
    o.x = (uint32_t)__half_as_ushort(__float2half_rn(v00.x)) |
          ((uint32_t)__half_as_ushort(__float2half_rn(v00.y)) << 16);
    o.y = (uint32_t)__half_as_ushort(__float2half_rn(v10.x)) |
          ((uint32_t)__half_as_ushort(__float2half_rn(v10.y)) << 16);
    o.z = (uint32_t)__half_as_ushort(__float2half_rn(v01.x)) |
          ((uint32_t)__half_as_ushort(__float2half_rn(v01.y)) << 16);
    o.w = (uint32_t)__half_as_ushort(__float2half_rn(v11.x)) |
          ((uint32_t)__half_as_ushort(__float2half_rn(v11.y)) << 16);
    g_xa[g] = o;
}

// ---------------- kernel 1: fused dequant + fp16 HMMA GEMM ----------------
// Grid (128, 1): blockIdx.x = N-tile (64 cols). CTA tile = 256(M) x 64(N).
// 256 threads = 8 warps as 4(M) x 2(N); warp tile 64x32 (mt=4, nt=4).
// Each weight group is dequantized exactly ONCE across the whole grid.
// A: cp.async gmem->SMEM ring (3 stages x 32KB, issued 2 iters ahead).
// B: packed LDG 1 iter ahead -> dequant -> SMEM (SW128) -> ldmatrix, 2 buffers.

__global__ void __launch_bounds__(256, 1)
linear2bit_gemm(const int4* __restrict__ wq,        // one int4 = one 16-value group
                const void* __restrict__ wn_raw,    // [NUM_GROUPS] norms (fp32 or fp16)
                const float* __restrict__ bias,     // [N]
                float* __restrict__ out)            // [M, N]
{
    extern __shared__ char smem[];
    const uint32_t sb = smem_u32(smem);
    const int tid = threadIdx.x;
    const int wid = tid >> 5;
    const int lid = tid & 31;
    const int ntile = blockIdx.x;                   // 64-col tile

    // ---- runtime dtype probe for weight_norm ----
    const float* wnf = (const float*)wn_raw;
    const __half* wnh = (const __half*)wn_raw;
    const float probe = __ldg(wnf);
    const bool norm_f32 = (probe > 6e-5f && probe < 0.06f);

    const int warp_m = wid >> 1;     // 4 x 64 rows
    const int warp_n = wid & 1;      // 2 x 32 cols

    // B ldmatrix per-lane unswizzled bases (two 16-row groups per warp)
    uint32_t brow[2];
    #pragma unroll
    for (int p = 0; p < 2; ++p)
        brow[p] = (uint32_t)((warp_n * 32 + p * 16 + (lid & 15)) * 128 + (lid >> 4) * 16);

    // ---- A cp.async: thread tid copies 8 uint4 chunks per iter (32KB) ----
    // flat = tid + 256*j (j=0..7); q = flat>>5 = mi*4+ks (mi 0..15); lane = flat&31
    const uint4* abase = g_xa;       // mtile == whole M
    auto cp_a = [&](int it, int slot) {
        uint32_t sdst = sb + SMEM_A + (uint32_t)slot * 32768u + (uint32_t)tid * 16u;
        #pragma unroll
        for (int j = 0; j < 8; ++j) {
            int flat = tid + 256 * j;
            int lane = flat & 31;
            int q = flat >> 5;              // mi*4 + ks
            int mi = q >> 2;
            int ks = q & 3;
            const uint4* src = abase + ((size_t)mi * (K / 16) + it * 4 + ks) * 32 + lane;
            asm volatile("cp.async.cg.shared.global [%0], [%1], 16;"
                         :: "r"(sdst + (uint32_t)j * 4096u), "l"(src) : "memory");
        }
        asm volatile("cp.async.commit_group;" ::: "memory");
    };

    // A LDS byte base within a slot for this warp/lane:
    // chunk index = (warp_m*4 + mt)*4 + ks, each chunk 32 lanes x 16B
    const uint32_t a_lds_off = (uint32_t)((warp_m * 4 * 4) * 32 + lid) * 16u;

    float acc[4][4][4];
    #pragma unroll
    for (int mt = 0; mt < 4; ++mt)
        #pragma unroll
        for (int nt = 0; nt < 4; ++nt)
            #pragma unroll
            for (int e = 0; e < 4; ++e) acc[mt][nt][e] = 0.0f;

    // B staging: 1 group per thread per iter (64 rows x 4 groups = 256)
    const int br = tid >> 2;        // B row in tile (0..63)
    const int bj = tid & 3;         // group within K-chunk (0..3)
    const int bg_base = (ntile * 64 + br) * 256 + bj;   // + it*4

    int4  bv;
    float bn;

    auto ldg_b = [&](int it) {
        int gidx = bg_base + it * 4;
        bv = __ldg(wq + gidx);
        bn = norm_f32 ? __ldg(wnf + gidx) : __half2float(__ldg(wnh + gidx));
    };
    auto sts_b = [&](int b) {
        char* bbuf = smem + SMEM_B + b * 8192;
        uint32_t o[8];
        dequant16(bv, bn, o);
        uint32_t off = (uint32_t)(br * 128 + bj * 32);
        *reinterpret_cast<int4*>(bbuf + sw128(off)) =
            make_int4((int)o[0], (int)o[1], (int)o[2], (int)o[3]);
        *reinterpret_cast<int4*>(bbuf + sw128(off + 16)) =
            make_int4((int)o[4], (int)o[5], (int)o[6], (int)o[7]);
    };

    // ---- prologue ----
    ldg_b(0);
    cp_a(0, 0);
    cp_a(1, 1);
    sts_b(0);
    asm volatile("cp.async.wait_group 1;" ::: "memory");   // slot 0 ready
    __syncthreads();

    #pragma unroll 1
    for (int it = 0; it < KITERS; ++it) {
        const int b = it & 1;
        if (it + 1 < KITERS) ldg_b(it + 1);

        const char* aslot = smem + SMEM_A + (it % 3) * 32768 + a_lds_off;
        const uint32_t bb = sb + SMEM_B + (uint32_t)b * 8192u;

        #pragma unroll
        for (int ks = 0; ks < 4; ++ks) {
            const uint32_t kb = (uint32_t)(ks * 32);   // 16 halves per k-step

            // A fragments for this ks: 4 x LDS.128 (mt = 0..3)
            uint4 af[4];
            #pragma unroll
            for (int mt = 0; mt < 4; ++mt)
                af[mt] = *reinterpret_cast<const uint4*>(
                    aslot + (mt * 4 + ks) * 32 * 16);

            uint32_t bf[2][4];
            #pragma unroll
            for (int p = 0; p < 2; ++p) {
                uint32_t addr = bb + sw128(brow[p] + kb);
                asm volatile(
                    "ldmatrix.sync.aligned.m8n8.x4.shared.b16 {%0,%1,%2,%3}, [%4];"
                    : "=r"(bf[p][0]), "=r"(bf[p][1]), "=r"(bf[p][2]), "=r"(bf[p][3])
                    : "r"(addr));
            }
            #pragma unroll
            for (int mt = 0; mt < 4; ++mt) {
                #pragma unroll
                for (int nt = 0; nt < 4; ++nt) {
                    uint32_t b0 = bf[nt >> 1][nt & 1];
                    uint32_t b1 = bf[nt >> 1][(nt & 1) + 2];
                    asm volatile(
                        "mma.sync.aligned.m16n8k16.row.col.f32.f16.f16.f32 "
                        "{%0,%1,%2,%3}, {%4,%5,%6,%7}, {%8,%9}, {%0,%1,%2,%3};"
                        : "+f"(acc[mt][nt][0]), "+f"(acc[mt][nt][1]),
                          "+f"(acc[mt][nt][2]), "+f"(acc[mt][nt][3])
                        : "r"(af[mt].x), "r"(af[mt].y),
                          "r"(af[mt].z), "r"(af[mt].w),
                          "r"(b0), "r"(b1));
                }
            }
        }

        if (it + 1 < KITERS) sts_b(b ^ 1);

        // Issue A copy for it+2 (clamped at tail; slot clobber is safe:
        // (it+2)%3 == (it-1)%3 which was already consumed).
        int itp = it + 2 < KITERS ? it + 2 : KITERS - 1;
        cp_a(itp, (it + 2) % 3);
        asm volatile("cp.async.wait_group 1;" ::: "memory");   // slot (it+1) ready
        __syncthreads();
    }

    // ---- epilogue: write accumulators + bias ----
    {
        const int mbase = warp_m * 64;
        const int nbase = ntile * 64 + warp_n * 32;
        const int rq = lid >> 2;             // row within m16 (0..7)
        const int cq = (lid & 3) * 2;        // col within n8 (0,2,4,6)
        #pragma unroll
        for (int mt = 0; mt < 4; ++mt) {
            #pragma unroll
            for (int nt = 0; nt < 4; ++nt) {
                int m0 = mbase + mt * 16 + rq;
                int n0 = nbase + nt * 8 + cq;
                float2 bsv = __ldg(reinterpret_cast<const float2*>(bias + n0));
                float2 v0, v1;
                v0.x = acc[mt][nt][0] + bsv.x;
                v0.y = acc[mt][nt][1] + bsv.y;
                v1.x = acc[mt][nt][2] + bsv.x;
                v1.y = acc[mt][nt][3] + bsv.y;
                *reinterpret_cast<float2*>(out + (size_t)m0 * N + n0) = v0;
                *reinterpret_cast<float2*>(out + (size_t)(m0 + 8) * N + n0) = v1;
            }
        }
    }
}

// ---------------- launch ----------------

extern "C" void kernel_launch(void* const* d_in, const int* in_sizes, int n_in,
                              void* d_out, int out_size) {
    (void)in_sizes; (void)n_in; (void)out_size;
    const float* x    = (const float*)d_in[0];
    const int4*  wq   = (const int4*)d_in[1];    // [NUM_GROUPS] groups of 4 int32
    const void*  wn   = (const void*)d_in[2];    // [NUM_GROUPS] norms
    const float* bias = (const float*)d_in[3];
    float*       out  = (float*)d_out;

    cudaFuncSetAttribute(linear2bit_gemm,
                         cudaFuncAttributeMaxDynamicSharedMemorySize, SMEM_TOTAL);

    convert_x_frag<<<(M / 16) * (K / 16) * 32 / 256, 256>>>(x);
    linear2bit_gemm<<<N / 64, 256, SMEM_TOTAL>>>(wq, wn, bias, out);
}